// round 1
// baseline (speedup 1.0000x reference)
#include <cuda_runtime.h>
#include <cstdint>

#define BATCH 256
#define L 4096
#define H 128

// ---------- packed f32x2 helpers (Blackwell sm_103a) ----------
__device__ __forceinline__ uint64_t pack2f(float a, float b) {
    uint64_t r; asm("mov.b64 %0, {%1, %2};" : "=l"(r) : "f"(a), "f"(b)); return r;
}
__device__ __forceinline__ float hsum2(uint64_t v) {
    float a, b; asm("mov.b64 {%0, %1}, %2;" : "=f"(a), "=f"(b) : "l"(v)); return a + b;
}
__device__ __forceinline__ uint64_t ffma2(uint64_t a, uint64_t b, uint64_t c) {
    uint64_t d; asm("fma.rn.f32x2 %0, %1, %2, %3;" : "=l"(d) : "l"(a), "l"(b), "l"(c)); return d;
}
__device__ __forceinline__ uint64_t fadd2(uint64_t a, uint64_t b) {
    uint64_t d; asm("add.rn.f32x2 %0, %1, %2;" : "=l"(d) : "l"(a), "l"(b)); return d;
}
__device__ __forceinline__ float elu1(float x) {
    return x > 0.f ? x : (__expf(x) - 1.f);
}

// One CTA handles 2 batch elements. 256 threads: thread = (i, s),
// i = tid>>1 in [0,128) = output hidden unit, s = tid&1 = k-half owner.
// Thread (i,s) owns W_c[l][k][i] for k in {8j+4s+m : j=0..15, m=0..3},
// kept in registers as packed f32x2. h vectors live in SMEM, ping-pong
// buffered by step parity; the two k-half partials meet via shfl_xor(1).
__global__ void __launch_bounds__(256, 1)
rnn_scan_kernel(const int* __restrict__ x,
                const float* __restrict__ W_in,
                const float* __restrict__ W_c,
                const float* __restrict__ W_out,
                const float* __restrict__ b_out,
                float* __restrict__ out)
{
    __shared__ __align__(16) float sh_h1[2][2 * H];   // [parity][batch*H]
    __shared__ __align__(16) float sh_h2[2][2 * H];
    __shared__ float sh_r[3 * H];                      // r vectors: spin0, spin1, zeros
    __shared__ float sh_wred[2][2][8];                 // [parity][batch][warp]
    __shared__ int   sh_x[2 * L];                      // 32 KB: both batch rows of x

    const int tid  = threadIdx.x;
    const int lane = tid & 31;
    const int warp = tid >> 5;
    const int i    = tid >> 1;     // output unit
    const int s    = tid & 1;      // k-half
    const int b0   = blockIdx.x * 2;

    // ---- stage x into SMEM (coalesced, both rows contiguous) ----
    const int* xg = x + (size_t)b0 * L;
    #pragma unroll 4
    for (int idx = tid; idx < 2 * L; idx += 256) sh_x[idx] = xg[idx];

    // ---- precompute the 3 possible r vectors ----
    if (tid < 2 * H) sh_r[tid] = elu1(W_in[tid]);   // W_in[d*128+c] row-major
    if (tid < H)     sh_r[2 * H + tid] = 0.f;       // prev = zero vector (t==0)

    // ---- zero the parity-0 h buffers (h0 = zeros) ----
    if (tid < 2 * H) { sh_h1[0][tid] = 0.f; sh_h2[0][tid] = 0.f; }

    // ---- load W_c columns into registers (packed pairs) ----
    uint64_t w1p[32], w2p[32];
    {
        const float* Wc0 = W_c;
        const float* Wc1 = W_c + H * H;
        #pragma unroll
        for (int j = 0; j < 16; ++j) {
            const int k0 = 8 * j + 4 * s;
            w1p[2*j]   = pack2f(Wc0[(k0+0)*H + i], Wc0[(k0+1)*H + i]);
            w1p[2*j+1] = pack2f(Wc0[(k0+2)*H + i], Wc0[(k0+3)*H + i]);
            w2p[2*j]   = pack2f(Wc1[(k0+0)*H + i], Wc1[(k0+1)*H + i]);
            w2p[2*j+1] = pack2f(Wc1[(k0+2)*H + i], Wc1[(k0+3)*H + i]);
        }
    }
    const float wout_i = W_out[i];     // W_out is [128,1]
    const float bout   = b_out[0];

    float acc = 0.f;                   // running log-prob (threads 0,1 only meaningful)
    __syncthreads();

    for (int t = 0; t < L; ++t) {
        const int p = t & 1;
        const float* h1r = &sh_h1[p][0];
        float*       h1w = &sh_h1[p ^ 1][0];
        const float* h2r = &sh_h2[p][0];
        float*       h2w = &sh_h2[p ^ 1][0];

        // ================= layer 1 matvec =================
        uint64_t a00 = 0, a01 = 0, a10 = 0, a11 = 0;
        #pragma unroll
        for (int j = 0; j < 16; ++j) {
            const ulonglong2 hv0 = *(const ulonglong2*)(h1r + 8*j + 4*s);
            const ulonglong2 hv1 = *(const ulonglong2*)(h1r + H + 8*j + 4*s);
            a00 = ffma2(w1p[2*j],   hv0.x, a00);
            a01 = ffma2(w1p[2*j+1], hv0.y, a01);
            a10 = ffma2(w1p[2*j],   hv1.x, a10);
            a11 = ffma2(w1p[2*j+1], hv1.y, a11);
        }
        float p0 = hsum2(fadd2(a00, a01));
        float p1 = hsum2(fadd2(a10, a11));
        p0 += __shfl_xor_sync(0xffffffffu, p0, 1);
        p1 += __shfl_xor_sync(0xffffffffu, p1, 1);

        // finalize batch 's': h1_new = elu(h1 @ Wc0) + r
        const int   prev = (t == 0) ? 2 : sh_x[s * L + t - 1];
        const float rv   = sh_r[prev * H + i];
        const float h1n  = elu1(s ? p1 : p0) + rv;
        h1w[s * H + i] = h1n;

        // ================= layer 2 matvec =================
        a00 = 0; a01 = 0; a10 = 0; a11 = 0;
        #pragma unroll
        for (int j = 0; j < 16; ++j) {
            const ulonglong2 hv0 = *(const ulonglong2*)(h2r + 8*j + 4*s);
            const ulonglong2 hv1 = *(const ulonglong2*)(h2r + H + 8*j + 4*s);
            a00 = ffma2(w2p[2*j],   hv0.x, a00);
            a01 = ffma2(w2p[2*j+1], hv0.y, a01);
            a10 = ffma2(w2p[2*j],   hv1.x, a10);
            a11 = ffma2(w2p[2*j+1], hv1.y, a11);
        }
        float q0 = hsum2(fadd2(a00, a01));
        float q1 = hsum2(fadd2(a10, a11));
        q0 += __shfl_xor_sync(0xffffffffu, q0, 1);
        q1 += __shfl_xor_sync(0xffffffffu, q1, 1);

        const float h2n = elu1(s ? q1 : q0) + h1n;   // + r (= h1_new for same batch)
        h2w[s * H + i] = h2n;

        // ============ output head: logit = h2 . W_out ============
        float term = h2n * wout_i;
        #pragma unroll
        for (int off = 2; off < 32; off <<= 1)
            term += __shfl_xor_sync(0xffffffffu, term, off);
        if (lane < 2) sh_wred[p][lane][warp] = term;   // lane0 -> batch0, lane1 -> batch1

        __syncthreads();   // single barrier per step: h ping-pong + wred visibility

        if (tid < 2) {     // tid == batch index within CTA
            float logit = bout;
            #pragma unroll
            for (int w = 0; w < 8; ++w) logit += sh_wred[p][tid][w];
            const int   xt  = sh_x[tid * L + t];
            const float m   = fmaxf(logit, 0.f);
            const float lse = m + __logf(__expf(-m) + __expf(logit - m));
            acc += 0.5f * ((xt ? logit : 0.f) - lse);
        }
    }

    if (tid < 2) out[b0 + tid] = acc;
}

extern "C" void kernel_launch(void* const* d_in, const int* in_sizes, int n_in,
                              void* d_out, int out_size)
{
    const int*   x     = (const int*)  d_in[0];
    const float* W_in  = (const float*)d_in[1];
    const float* W_c   = (const float*)d_in[2];
    const float* W_out = (const float*)d_in[3];
    const float* b_out = (const float*)d_in[4];

    rnn_scan_kernel<<<BATCH / 2, 256>>>(x, W_in, W_c, W_out, b_out, (float*)d_out);
}